// round 13
// baseline (speedup 1.0000x reference)
#include <cuda_runtime.h>
#include <cuda_bf16.h>

#define B_ 8
#define P_ 4096
#define G_ 96
#define NT 512
#define LOG_NT 9
#define NW (NT / 32)
#define CPT (P_ / NT)           /* 8 columns per thread */
#define PBLK 128                /* p-tiles of 32 in transpose */
#define BIGF 1e9f
#define INFF 3.402823466e+38f

__device__ float g_costT[(size_t)B_ * G_ * P_];
__device__ unsigned long long g_part[(size_t)B_ * G_ * PBLK]; // per-tile packed mins

__device__ __forceinline__ unsigned int f2ord(float f) {
    unsigned int u = __float_as_uint(f);
    return ((int)u < 0) ? ~u : (u ^ 0x80000000u);
}
__device__ __forceinline__ float ord2f(unsigned int k) {
    unsigned int u = (k & 0x80000000u) ? (k ^ 0x80000000u) : ~k;
    return __uint_as_float(u);
}

// ---------------------------------------------------------------------------
// Kernel 1: fused cost + transpose (32x32 tile, 4 elems/thread) + per-tile
// row-min partials.  costT[b][g][p] = cd[b][p][g] - 2*gi[b][p][g]
// (unchanged from R9/R10 — measured-good config)
// ---------------------------------------------------------------------------
__global__ __launch_bounds__(256, 8)
void cost_transpose_kernel(const float* __restrict__ cd,
                           const float* __restrict__ gi) {
    __shared__ float tile[32][33];
    __shared__ unsigned long long pmin[32][8];
    const int b  = blockIdx.z;
    const int p0 = blockIdx.x * 32;
    const int g0 = blockIdx.y * 32;
    const int tx = threadIdx.x;              // g lane
    const int ty = threadIdx.y;              // p lane (0..7)

    float c[4], g[4];
    #pragma unroll
    for (int r = 0; r < 4; r++) {
        size_t iidx = ((size_t)b * P_ + (p0 + ty + 8 * r)) * G_ + (g0 + tx);
        c[r] = __ldg(cd + iidx);
        g[r] = __ldg(gi + iidx);
    }
    float bestv = INFF;
    int   bestp = 0;
    #pragma unroll
    for (int r = 0; r < 4; r++) {
        float val = c[r] - 2.0f * g[r];      // 2*g exact in fp32
        tile[ty + 8 * r][tx] = val;
        if (val < bestv) { bestv = val; bestp = p0 + ty + 8 * r; } // ascending p
    }
    pmin[tx][ty] = ((unsigned long long)f2ord(bestv) << 32) | (unsigned int)bestp;
    __syncthreads();

    #pragma unroll
    for (int r = 0; r < 4; r++)
        g_costT[((size_t)b * G_ + (g0 + ty + 8 * r)) * P_ + (p0 + tx)]
            = tile[tx][ty + 8 * r];

    if (ty == 0) {
        unsigned long long m = pmin[tx][0];
        #pragma unroll
        for (int w = 1; w < 8; w++) if (pmin[tx][w] < m) m = pmin[tx][w];
        g_part[((size_t)b * G_ + (g0 + tx)) * PBLK + blockIdx.x] = m;
    }

#if __CUDA_ARCH__ >= 900
    cudaTriggerProgrammaticLaunchCompletion();
#endif
}

// ---------------------------------------------------------------------------
// Kernel 2: one block per batch, NT=512.  PDL prologue overlap, then
// partial-reduce + greedy dual-feasible init + JV augmenting paths.
// ---------------------------------------------------------------------------
__global__ __launch_bounds__(NT, 1)
void matcher_kernel(const int* __restrict__ nactual,
                    float* __restrict__ out) {
    extern __shared__ char smem[];
    unsigned long long* rowarg_s = (unsigned long long*)smem;   // [G_]
    int*   row4col  = (int*)(rowarg_s + G_);           // [P_]
    float* sh_dump  = (float*)(row4col + P_);          // [P_]
    int*   path_dump= (int*)(sh_dump + P_);            // [P_] (aliased as colowner)
    float* u        = (float*)(path_dump + P_);        // [G_]
    int*   col4row  = (int*)(u + G_);                  // [G_]
    uint4* partials = (uint4*)(col4row + G_);          // [2][NW]
    unsigned char* SR = (unsigned char*)(partials + 2 * NW); // [G_]

    const int b = blockIdx.x;
    const int t = threadIdx.x;
    const int wid = t >> 5, lane = t & 31;
    const float* cost = g_costT + (size_t)b * G_ * P_;
    const int nact = nactual[b];

    float vreg[CPT];
    float shreg[CPT];
    int   pathreg[CPT];
    unsigned int scmask;

    // ---- prologue: everything independent of the transpose ----
    float* oi = out + (size_t)b * P_;
    float* om = out + (size_t)B_ * P_ + (size_t)b * P_;
    #pragma unroll
    for (int k = 0; k < CPT; k++) vreg[k] = 0.0f;
    int* colowner = path_dump;
    for (int j = t; j < P_; j += NT) {
        row4col[j] = -1; colowner[j] = 0x7fffffff;
        oi[j] = 0.0f; om[j] = 0.0f;
    }
    if (t < G_) col4row[t] = -1;

#if __CUDA_ARCH__ >= 900
    cudaGridDependencySynchronize();       // wait for transpose results
#endif

    // (a) reduce partials: 16 warps x 6 rows
    #pragma unroll
    for (int rr = 0; rr < G_ / NW; rr++) {
        const int row = wid * (G_ / NW) + rr;
        const unsigned long long* pp = g_part + ((size_t)b * G_ + row) * PBLK;
        unsigned long long m = pp[lane];
        #pragma unroll
        for (int l = 1; l < PBLK / 32; l++) {
            unsigned long long o = pp[lane + 32 * l];
            if (o < m) m = o;
        }
        #pragma unroll
        for (int off = 16; off; off >>= 1) {
            unsigned long long o = __shfl_down_sync(0xffffffffu, m, off);
            if (o < m) m = o;
        }
        if (lane == 0) rowarg_s[row] = m;
    }
    __syncthreads();

    // (b) greedy: row i wants its argmin column; lowest row index wins
    unsigned long long myarg = 0;
    if (t < G_ && t < nact) {
        myarg = rowarg_s[t];
        u[t] = ord2f((unsigned int)(myarg >> 32));     // u[i] = row min (exact)
        atomicMin(&colowner[(int)(myarg & 0xffffffffu)], t);
    }
    __syncthreads();
    if (t < G_ && t < nact) {
        int j = (int)(myarg & 0xffffffffu);
        if (colowner[j] == t) { col4row[t] = j; row4col[j] = t; }
    }
    __syncthreads();

    // (c) augment the (rare) unassigned rows
    for (int i = 0; i < nact; ++i) {
        if (col4row[i] >= 0) continue;

        #pragma unroll
        for (int k = 0; k < CPT; k++) { shreg[k] = BIGF; pathreg[k] = -1; }
        scmask = 0u;
        if (t < G_) SR[t] = 0;
        __syncthreads();           // barrier A

        int   cur    = i;
        float ucur   = u[i];
        float minval = 0.0f;
        int   sink   = -1;
        int   parity = 0;

        while (sink < 0) {
            if (t == 0) SR[cur] = 1;
            const float* crow = cost + (size_t)cur * P_;

            float c[CPT];
            #pragma unroll
            for (int k = 0; k < CPT; k++) c[k] = __ldg(crow + t + k * NT);

            float bestv = INFF;
            int   bestj = P_;
            #pragma unroll
            for (int k = 0; k < CPT; k++) {
                if (!((scmask >> k) & 1u)) {
                    float red = ((minval + c[k]) - ucur) - vreg[k];
                    if (red < shreg[k]) { shreg[k] = red; pathreg[k] = cur; }
                    if (shreg[k] < bestv) { bestv = shreg[k]; bestj = t + k * NT; }
                }
            }
            unsigned int key    = f2ord(bestv);
            unsigned int minkey = __reduce_min_sync(0xffffffffu, key);
            unsigned int jc     = (key == minkey) ? (unsigned int)bestj : 0xffffffffu;
            unsigned int minj   = __reduce_min_sync(0xffffffffu, jc);

            if (lane == 0) {
                int r = row4col[minj];
                float ur = (r >= 0) ? u[r] : 0.0f;
                partials[parity * NW + wid] =
                    make_uint4(minkey, minj, (unsigned int)r, __float_as_uint(ur));
            }
            __syncthreads();

            uint4 best = partials[parity * NW];
            #pragma unroll
            for (int w = 1; w < NW; w++) {
                uint4 pw = partials[parity * NW + w];
                if (pw.x < best.x || (pw.x == best.x && pw.y < best.y)) best = pw;
            }
            minval = ord2f(best.x);
            int bj = (int)best.y;
            if ((bj & (NT - 1)) == t) scmask |= 1u << (bj >> LOG_NT);
            if ((int)best.z < 0) { sink = bj; }
            else { cur = (int)best.z; ucur = __uint_as_float(best.w); }
            parity ^= 1;
        }

        #pragma unroll
        for (int k = 0; k < CPT; k++) {
            sh_dump[t + k * NT]   = shreg[k];
            path_dump[t + k * NT] = pathreg[k];
        }
        __syncthreads();           // barrier B

        if (t == 0) u[i] += minval;
        if (t < G_ && t != i && SR[t]) {
            int c4 = col4row[t]; if (c4 < 0) c4 = 0;
            u[t] = (u[t] + minval) - sh_dump[c4];
        }
        #pragma unroll
        for (int k = 0; k < CPT; k++)
            if ((scmask >> k) & 1u) vreg[k] = vreg[k] - (minval - shreg[k]);
        __syncthreads();           // barrier C

        if (t == 0) {
            int j = sink;
            while (true) {
                int r = path_dump[j];
                row4col[j] = r;
                int jn = col4row[r];
                col4row[r] = j;
                if (r == i) break;
                j = jn;
            }
        }
        __syncthreads();
    }

    // final scatter (outputs already zeroed in prologue)
    if (t < G_ && t < nact) {
        int p = col4row[t];
        if (p >= 0) { oi[p] = (float)t; om[p] = 1.0f; }
    }
}

// ---------------------------------------------------------------------------
static const int MATCHER_SMEM =
    G_ * 8                     /* rowarg_s */
    + P_ * 4 * 3               /* row4col, sh_dump, path_dump/colowner */
    + G_ * 4 * 2               /* u, col4row */
    + 2 * NW * 16              /* uint4 partials */
    + G_ + 64;                 /* SR + pad */

extern "C" void kernel_launch(void* const* d_in, const int* in_sizes, int n_in,
                              void* d_out, int out_size) {
    const float* cd   = (const float*)d_in[0];
    const float* gi   = (const float*)d_in[1];
    const int*   nact = (const int*)d_in[2];

    float* out = (float*)d_out;                  // [2, B, P] float32

    dim3 tb(32, 8);
    dim3 gb(P_ / 32, G_ / 32, B_);
    cost_transpose_kernel<<<gb, tb>>>(cd, gi);

    cudaFuncSetAttribute(matcher_kernel,
                         cudaFuncAttributeMaxDynamicSharedMemorySize, MATCHER_SMEM);

    cudaLaunchConfig_t cfg = {};
    cfg.gridDim = dim3(B_);
    cfg.blockDim = dim3(NT);
    cfg.dynamicSmemBytes = MATCHER_SMEM;
    cfg.stream = 0;
    cudaLaunchAttribute attr[1];
    attr[0].id = cudaLaunchAttributeProgrammaticStreamSerialization;
    attr[0].val.programmaticStreamSerializationAllowed = 1;
    cfg.attrs = attr;
    cfg.numAttrs = 1;
    cudaLaunchKernelEx(&cfg, matcher_kernel, nact, out);
}

// round 15
// speedup vs baseline: 1.7391x; 1.7391x over previous
#include <cuda_runtime.h>
#include <cuda_bf16.h>

#define B_ 8
#define P_ 4096
#define G_ 96
#define NT 256
#define LOG_NT 8
#define NW (NT / 32)
#define CPT (P_ / NT)           /* 16 columns per thread */
#define PBLK 128                /* p-tiles of 32 in transpose */
#define BIGF 1e9f
#define INFF 3.402823466e+38f

__device__ float g_costT[(size_t)B_ * G_ * P_];
__device__ unsigned long long g_part[(size_t)B_ * G_ * PBLK]; // per-tile packed mins

__device__ __forceinline__ unsigned int f2ord(float f) {
    unsigned int u = __float_as_uint(f);
    return ((int)u < 0) ? ~u : (u ^ 0x80000000u);
}
__device__ __forceinline__ float ord2f(unsigned int k) {
    unsigned int u = (k & 0x80000000u) ? (k ^ 0x80000000u) : ~k;
    return __uint_as_float(u);
}

// ---------------------------------------------------------------------------
// Kernel 1: fused cost + transpose (32x32 tile, 4 elems/thread) + per-tile
// row-min partials.  costT[b][g][p] = cd[b][p][g] - 2*gi[b][p][g]
// (unchanged from R10 — measured-good config)
// ---------------------------------------------------------------------------
__global__ __launch_bounds__(256, 8)
void cost_transpose_kernel(const float* __restrict__ cd,
                           const float* __restrict__ gi) {
    __shared__ float tile[32][33];
    __shared__ unsigned long long pmin[32][8];
    const int b  = blockIdx.z;
    const int p0 = blockIdx.x * 32;
    const int g0 = blockIdx.y * 32;
    const int tx = threadIdx.x;              // g lane
    const int ty = threadIdx.y;              // p lane (0..7)

    float c[4], g[4];
    #pragma unroll
    for (int r = 0; r < 4; r++) {
        size_t iidx = ((size_t)b * P_ + (p0 + ty + 8 * r)) * G_ + (g0 + tx);
        c[r] = __ldg(cd + iidx);
        g[r] = __ldg(gi + iidx);
    }
    float bestv = INFF;
    int   bestp = 0;
    #pragma unroll
    for (int r = 0; r < 4; r++) {
        float val = c[r] - 2.0f * g[r];      // 2*g exact in fp32
        tile[ty + 8 * r][tx] = val;
        if (val < bestv) { bestv = val; bestp = p0 + ty + 8 * r; } // ascending p
    }
    pmin[tx][ty] = ((unsigned long long)f2ord(bestv) << 32) | (unsigned int)bestp;
    __syncthreads();

    #pragma unroll
    for (int r = 0; r < 4; r++)
        g_costT[((size_t)b * G_ + (g0 + ty + 8 * r)) * P_ + (p0 + tx)]
            = tile[tx][ty + 8 * r];

    if (ty == 0) {
        unsigned long long m = pmin[tx][0];
        #pragma unroll
        for (int w = 1; w < 8; w++) if (pmin[tx][w] < m) m = pmin[tx][w];
        g_part[((size_t)b * G_ + (g0 + tx)) * PBLK + blockIdx.x] = m;
    }

#if __CUDA_ARCH__ >= 900
    cudaTriggerProgrammaticLaunchCompletion();
#endif
}

// ---------------------------------------------------------------------------
// Kernel 2: one block per batch, NT=256.  PDL prologue overlap, then
// partial-reduce + greedy init + JV augmenting paths over a conflict bitmask.
// ---------------------------------------------------------------------------
__global__ __launch_bounds__(NT, 1)
void matcher_kernel(const int* __restrict__ nactual,
                    float* __restrict__ out) {
    extern __shared__ char smem[];
    unsigned long long* rowarg_s = (unsigned long long*)smem;   // [G_]
    int*   row4col  = (int*)(rowarg_s + G_);           // [P_]
    float* sh_dump  = (float*)(row4col + P_);          // [P_]
    int*   path_dump= (int*)(sh_dump + P_);            // [P_] (aliased as colowner)
    float* u        = (float*)(path_dump + P_);        // [G_]
    int*   col4row  = (int*)(u + G_);                  // [G_]
    uint4* partials = (uint4*)(col4row + G_);          // [2][NW]
    unsigned int* confmask = (unsigned int*)(partials + 2 * NW); // [3]
    unsigned char* SR = (unsigned char*)(confmask + 4);          // [G_]

    const int b = blockIdx.x;
    const int t = threadIdx.x;
    const int wid = t >> 5, lane = t & 31;
    const float* cost = g_costT + (size_t)b * G_ * P_;
    const int nact = nactual[b];

    float vreg[CPT];
    float shreg[CPT];
    int   pathreg[CPT];
    unsigned int scmask;

    // ---- prologue: everything independent of the transpose ----
    float* oi = out + (size_t)b * P_;
    float* om = out + (size_t)B_ * P_ + (size_t)b * P_;
    #pragma unroll
    for (int k = 0; k < CPT; k++) vreg[k] = 0.0f;
    int* colowner = path_dump;
    for (int j = t; j < P_; j += NT) {
        row4col[j] = -1; colowner[j] = 0x7fffffff;
        oi[j] = 0.0f; om[j] = 0.0f;
    }
    if (t < G_) col4row[t] = -1;

#if __CUDA_ARCH__ >= 900
    cudaGridDependencySynchronize();       // wait for transpose results
#endif

    // (a) reduce partials: 8 warps x 12 rows
    #pragma unroll
    for (int rr = 0; rr < G_ / NW; rr++) {
        const int row = wid * (G_ / NW) + rr;
        const unsigned long long* pp = g_part + ((size_t)b * G_ + row) * PBLK;
        unsigned long long m = pp[lane];
        #pragma unroll
        for (int l = 1; l < PBLK / 32; l++) {
            unsigned long long o = pp[lane + 32 * l];
            if (o < m) m = o;
        }
        #pragma unroll
        for (int off = 16; off; off >>= 1) {
            unsigned long long o = __shfl_down_sync(0xffffffffu, m, off);
            if (o < m) m = o;
        }
        if (lane == 0) rowarg_s[row] = m;
    }
    __syncthreads();

    // (b) greedy: row i wants its argmin column; lowest row index wins
    unsigned long long myarg = 0;
    if (t < G_ && t < nact) {
        myarg = rowarg_s[t];
        u[t] = ord2f((unsigned int)(myarg >> 32));     // u[i] = row min (exact)
        atomicMin(&colowner[(int)(myarg & 0xffffffffu)], t);
    }
    __syncthreads();
    if (t < G_ && t < nact) {
        int j = (int)(myarg & 0xffffffffu);
        if (colowner[j] == t) { col4row[t] = j; row4col[j] = t; }
    }
    __syncthreads();

    // build conflict bitmask: first 3 warps ballot over their 32 rows each
    if (wid < 3) {
        int row = t;                                   // t = wid*32 + lane < 96
        int conf = (row < nact && col4row[row] < 0) ? 1 : 0;
        unsigned int m = __ballot_sync(0xffffffffu, conf);
        if (lane == 0) confmask[wid] = m;
    }
    __syncthreads();

    // (c) augment the conflicted rows (ascending i), uniform bit iteration
    #pragma unroll 1
    for (int w = 0; w < 3; w++) {
        unsigned int cm = confmask[w];
        #pragma unroll 1
        while (cm) {
            const int i = 32 * w + (__ffs(cm) - 1);
            cm &= cm - 1;

            #pragma unroll
            for (int k = 0; k < CPT; k++) { shreg[k] = BIGF; pathreg[k] = -1; }
            scmask = 0u;
            if (t < G_) SR[t] = 0;
            __syncthreads();           // barrier A

            int   cur    = i;
            float ucur   = u[i];
            float minval = 0.0f;
            int   sink   = -1;
            int   parity = 0;

            while (sink < 0) {
                if (t == 0) SR[cur] = 1;
                const float* crow = cost + (size_t)cur * P_;

                float c[CPT];
                #pragma unroll
                for (int k = 0; k < CPT; k++) c[k] = __ldg(crow + t + k * NT);

                float bestv = INFF;
                int   bestj = P_;
                #pragma unroll
                for (int k = 0; k < CPT; k++) {
                    if (!((scmask >> k) & 1u)) {
                        float red = ((minval + c[k]) - ucur) - vreg[k];
                        if (red < shreg[k]) { shreg[k] = red; pathreg[k] = cur; }
                        if (shreg[k] < bestv) { bestv = shreg[k]; bestj = t + k * NT; }
                    }
                }
                unsigned int key    = f2ord(bestv);
                unsigned int minkey = __reduce_min_sync(0xffffffffu, key);
                unsigned int jc     = (key == minkey) ? (unsigned int)bestj : 0xffffffffu;
                unsigned int minj   = __reduce_min_sync(0xffffffffu, jc);

                if (lane == 0) {
                    int r = row4col[minj];
                    float ur = (r >= 0) ? u[r] : 0.0f;
                    partials[parity * NW + wid] =
                        make_uint4(minkey, minj, (unsigned int)r, __float_as_uint(ur));
                }
                __syncthreads();

                uint4 best = partials[parity * NW];
                #pragma unroll
                for (int ww = 1; ww < NW; ww++) {
                    uint4 pw = partials[parity * NW + ww];
                    if (pw.x < best.x || (pw.x == best.x && pw.y < best.y)) best = pw;
                }
                minval = ord2f(best.x);
                int bj = (int)best.y;
                if ((bj & (NT - 1)) == t) scmask |= 1u << (bj >> LOG_NT);
                if ((int)best.z < 0) { sink = bj; }
                else { cur = (int)best.z; ucur = __uint_as_float(best.w); }
                parity ^= 1;
            }

            #pragma unroll
            for (int k = 0; k < CPT; k++) {
                sh_dump[t + k * NT]   = shreg[k];
                path_dump[t + k * NT] = pathreg[k];
            }
            __syncthreads();           // barrier B

            if (t == 0) u[i] += minval;
            if (t < G_ && t != i && SR[t]) {
                int c4 = col4row[t]; if (c4 < 0) c4 = 0;
                u[t] = (u[t] + minval) - sh_dump[c4];
            }
            #pragma unroll
            for (int k = 0; k < CPT; k++)
                if ((scmask >> k) & 1u) vreg[k] = vreg[k] - (minval - shreg[k]);
            __syncthreads();           // barrier C

            if (t == 0) {
                int j = sink;
                while (true) {
                    int r = path_dump[j];
                    row4col[j] = r;
                    int jn = col4row[r];
                    col4row[r] = j;
                    if (r == i) break;
                    j = jn;
                }
            }
            __syncthreads();
        }
    }

    // final scatter (outputs already zeroed in prologue)
    if (t < G_ && t < nact) {
        int p = col4row[t];
        if (p >= 0) { oi[p] = (float)t; om[p] = 1.0f; }
    }
}

// ---------------------------------------------------------------------------
static const int MATCHER_SMEM =
    G_ * 8                     /* rowarg_s */
    + P_ * 4 * 3               /* row4col, sh_dump, path_dump/colowner */
    + G_ * 4 * 2               /* u, col4row */
    + 2 * NW * 16              /* uint4 partials */
    + 16                       /* confmask */
    + G_ + 64;                 /* SR + pad */

extern "C" void kernel_launch(void* const* d_in, const int* in_sizes, int n_in,
                              void* d_out, int out_size) {
    const float* cd   = (const float*)d_in[0];
    const float* gi   = (const float*)d_in[1];
    const int*   nact = (const int*)d_in[2];

    float* out = (float*)d_out;                  // [2, B, P] float32

    dim3 tb(32, 8);
    dim3 gb(P_ / 32, G_ / 32, B_);
    cost_transpose_kernel<<<gb, tb>>>(cd, gi);

    cudaFuncSetAttribute(matcher_kernel,
                         cudaFuncAttributeMaxDynamicSharedMemorySize, MATCHER_SMEM);

    cudaLaunchConfig_t cfg = {};
    cfg.gridDim = dim3(B_);
    cfg.blockDim = dim3(NT);
    cfg.dynamicSmemBytes = MATCHER_SMEM;
    cfg.stream = 0;
    cudaLaunchAttribute attr[1];
    attr[0].id = cudaLaunchAttributeProgrammaticStreamSerialization;
    attr[0].val.programmaticStreamSerializationAllowed = 1;
    cfg.attrs = attr;
    cfg.numAttrs = 1;
    cudaLaunchKernelEx(&cfg, matcher_kernel, nact, out);
}

// round 16
// speedup vs baseline: 1.8891x; 1.0862x over previous
#include <cuda_runtime.h>
#include <cuda_bf16.h>

#define B_ 8
#define P_ 4096
#define G_ 96
#define NT 256
#define LOG_NT 8
#define NW (NT / 32)
#define CPT (P_ / NT)           /* 16 columns per thread */
#define BIGF 1e9f
#define INFF 3.402823466e+38f

__device__ float g_costT[(size_t)B_ * G_ * P_];
// complemented packed row-min accumulator: max(~((key<<32)|p)) == min((key<<32)|p)
// zero-initialized  =>  ~0 = +inf key. Matcher resets to 0 after use (graph replay).
__device__ unsigned long long g_rowarg[B_ * G_];

__device__ __forceinline__ unsigned int f2ord(float f) {
    unsigned int u = __float_as_uint(f);
    return ((int)u < 0) ? ~u : (u ^ 0x80000000u);
}
__device__ __forceinline__ float ord2f(unsigned int k) {
    unsigned int u = (k & 0x80000000u) ? (k ^ 0x80000000u) : ~k;
    return __uint_as_float(u);
}

// ---------------------------------------------------------------------------
// Kernel 1: fused cost + transpose (32x32 tile, 4 elems/thread); per-tile row
// mins accumulated straight into g_rowarg via atomicMax on complemented keys.
// costT[b][g][p] = cd[b][p][g] - 2*gi[b][p][g]
// ---------------------------------------------------------------------------
__global__ __launch_bounds__(256, 8)
void cost_transpose_kernel(const float* __restrict__ cd,
                           const float* __restrict__ gi) {
    __shared__ float tile[32][33];
    __shared__ unsigned long long pmin[32][8];
    const int b  = blockIdx.z;
    const int p0 = blockIdx.x * 32;
    const int g0 = blockIdx.y * 32;
    const int tx = threadIdx.x;              // g lane
    const int ty = threadIdx.y;              // p lane (0..7)

    float c[4], g[4];
    #pragma unroll
    for (int r = 0; r < 4; r++) {
        size_t iidx = ((size_t)b * P_ + (p0 + ty + 8 * r)) * G_ + (g0 + tx);
        c[r] = __ldg(cd + iidx);
        g[r] = __ldg(gi + iidx);
    }
    float bestv = INFF;
    int   bestp = 0;
    #pragma unroll
    for (int r = 0; r < 4; r++) {
        float val = c[r] - 2.0f * g[r];      // 2*g exact in fp32
        tile[ty + 8 * r][tx] = val;
        if (val < bestv) { bestv = val; bestp = p0 + ty + 8 * r; } // ascending p
    }
    pmin[tx][ty] = ((unsigned long long)f2ord(bestv) << 32) | (unsigned int)bestp;
    __syncthreads();

    #pragma unroll
    for (int r = 0; r < 4; r++)
        g_costT[((size_t)b * G_ + (g0 + ty + 8 * r)) * P_ + (p0 + tx)]
            = tile[tx][ty + 8 * r];

    if (ty == 0) {
        unsigned long long m = pmin[tx][0];
        #pragma unroll
        for (int w = 1; w < 8; w++) if (pmin[tx][w] < m) m = pmin[tx][w];
        atomicMax(&g_rowarg[b * G_ + g0 + tx], ~m);
    }

#if __CUDA_ARCH__ >= 900
    cudaTriggerProgrammaticLaunchCompletion();
#endif
}

// ---------------------------------------------------------------------------
// Kernel 2: one block per batch, NT=256.  PDL prologue overlap, then read
// g_rowarg directly (+ reset for next replay), greedy init, JV augmenting
// paths over a conflict bitmask.
// ---------------------------------------------------------------------------
__global__ __launch_bounds__(NT, 1)
void matcher_kernel(const int* __restrict__ nactual,
                    float* __restrict__ out) {
    extern __shared__ char smem[];
    unsigned long long* rowarg_s = (unsigned long long*)smem;   // [G_]
    int*   row4col  = (int*)(rowarg_s + G_);           // [P_]
    float* sh_dump  = (float*)(row4col + P_);          // [P_]
    int*   path_dump= (int*)(sh_dump + P_);            // [P_] (aliased as colowner)
    float* u        = (float*)(path_dump + P_);        // [G_]
    int*   col4row  = (int*)(u + G_);                  // [G_]
    uint4* partials = (uint4*)(col4row + G_);          // [2][NW]
    unsigned int* confmask = (unsigned int*)(partials + 2 * NW); // [3]
    unsigned char* SR = (unsigned char*)(confmask + 4);          // [G_]

    const int b = blockIdx.x;
    const int t = threadIdx.x;
    const int wid = t >> 5, lane = t & 31;
    const float* cost = g_costT + (size_t)b * G_ * P_;
    const int nact = nactual[b];

    float vreg[CPT];
    float shreg[CPT];
    int   pathreg[CPT];
    unsigned int scmask;

    // ---- prologue: everything independent of the transpose ----
    float* oi = out + (size_t)b * P_;
    float* om = out + (size_t)B_ * P_ + (size_t)b * P_;
    #pragma unroll
    for (int k = 0; k < CPT; k++) vreg[k] = 0.0f;
    int* colowner = path_dump;
    for (int j = t; j < P_; j += NT) {
        row4col[j] = -1; colowner[j] = 0x7fffffff;
        oi[j] = 0.0f; om[j] = 0.0f;
    }
    if (t < G_) col4row[t] = -1;

#if __CUDA_ARCH__ >= 900
    cudaGridDependencySynchronize();       // wait for transpose results
#endif

    // (a) read accumulated row argmins; reset accumulator for next replay
    if (t < G_) {
        unsigned long long m = ~g_rowarg[b * G_ + t];
        rowarg_s[t] = m;
        g_rowarg[b * G_ + t] = 0ull;
    }
    __syncthreads();

    // (b) greedy: row i wants its argmin column; lowest row index wins
    unsigned long long myarg = 0;
    if (t < G_ && t < nact) {
        myarg = rowarg_s[t];
        u[t] = ord2f((unsigned int)(myarg >> 32));     // u[i] = row min (exact)
        atomicMin(&colowner[(int)(myarg & 0xffffffffu)], t);
    }
    __syncthreads();
    if (t < G_ && t < nact) {
        int j = (int)(myarg & 0xffffffffu);
        if (colowner[j] == t) { col4row[t] = j; row4col[j] = t; }
    }
    __syncthreads();

    // build conflict bitmask: first 3 warps ballot over their 32 rows each
    if (wid < 3) {
        int row = t;                                   // t = wid*32 + lane < 96
        int conf = (row < nact && col4row[row] < 0) ? 1 : 0;
        unsigned int m = __ballot_sync(0xffffffffu, conf);
        if (lane == 0) confmask[wid] = m;
    }
    __syncthreads();

    // (c) augment the conflicted rows (ascending i), uniform bit iteration
    #pragma unroll 1
    for (int w = 0; w < 3; w++) {
        unsigned int cm = confmask[w];
        #pragma unroll 1
        while (cm) {
            const int i = 32 * w + (__ffs(cm) - 1);
            cm &= cm - 1;

            #pragma unroll
            for (int k = 0; k < CPT; k++) { shreg[k] = BIGF; pathreg[k] = -1; }
            scmask = 0u;
            if (t < G_) SR[t] = 0;
            __syncthreads();           // barrier A

            int   cur    = i;
            float ucur   = u[i];
            float minval = 0.0f;
            int   sink   = -1;
            int   parity = 0;

            while (sink < 0) {
                if (t == 0) SR[cur] = 1;
                const float* crow = cost + (size_t)cur * P_;

                float c[CPT];
                #pragma unroll
                for (int k = 0; k < CPT; k++) c[k] = __ldg(crow + t + k * NT);

                float bestv = INFF;
                int   bestj = P_;
                #pragma unroll
                for (int k = 0; k < CPT; k++) {
                    if (!((scmask >> k) & 1u)) {
                        float red = ((minval + c[k]) - ucur) - vreg[k];
                        if (red < shreg[k]) { shreg[k] = red; pathreg[k] = cur; }
                        if (shreg[k] < bestv) { bestv = shreg[k]; bestj = t + k * NT; }
                    }
                }
                unsigned int key    = f2ord(bestv);
                unsigned int minkey = __reduce_min_sync(0xffffffffu, key);
                unsigned int jc     = (key == minkey) ? (unsigned int)bestj : 0xffffffffu;
                unsigned int minj   = __reduce_min_sync(0xffffffffu, jc);

                if (lane == 0) {
                    int r = row4col[minj];
                    float ur = (r >= 0) ? u[r] : 0.0f;
                    partials[parity * NW + wid] =
                        make_uint4(minkey, minj, (unsigned int)r, __float_as_uint(ur));
                }
                __syncthreads();

                uint4 best = partials[parity * NW];
                #pragma unroll
                for (int ww = 1; ww < NW; ww++) {
                    uint4 pw = partials[parity * NW + ww];
                    if (pw.x < best.x || (pw.x == best.x && pw.y < best.y)) best = pw;
                }
                minval = ord2f(best.x);
                int bj = (int)best.y;
                if ((bj & (NT - 1)) == t) scmask |= 1u << (bj >> LOG_NT);
                if ((int)best.z < 0) { sink = bj; }
                else { cur = (int)best.z; ucur = __uint_as_float(best.w); }
                parity ^= 1;
            }

            #pragma unroll
            for (int k = 0; k < CPT; k++) {
                sh_dump[t + k * NT]   = shreg[k];
                path_dump[t + k * NT] = pathreg[k];
            }
            __syncthreads();           // barrier B

            if (t == 0) u[i] += minval;
            if (t < G_ && t != i && SR[t]) {
                int c4 = col4row[t]; if (c4 < 0) c4 = 0;
                u[t] = (u[t] + minval) - sh_dump[c4];
            }
            #pragma unroll
            for (int k = 0; k < CPT; k++)
                if ((scmask >> k) & 1u) vreg[k] = vreg[k] - (minval - shreg[k]);
            __syncthreads();           // barrier C

            if (t == 0) {
                int j = sink;
                while (true) {
                    int r = path_dump[j];
                    row4col[j] = r;
                    int jn = col4row[r];
                    col4row[r] = j;
                    if (r == i) break;
                    j = jn;
                }
            }
            __syncthreads();
        }
    }

    // final scatter (outputs already zeroed in prologue)
    if (t < G_ && t < nact) {
        int p = col4row[t];
        if (p >= 0) { oi[p] = (float)t; om[p] = 1.0f; }
    }
}

// ---------------------------------------------------------------------------
static const int MATCHER_SMEM =
    G_ * 8                     /* rowarg_s */
    + P_ * 4 * 3               /* row4col, sh_dump, path_dump/colowner */
    + G_ * 4 * 2               /* u, col4row */
    + 2 * NW * 16              /* uint4 partials */
    + 16                       /* confmask */
    + G_ + 64;                 /* SR + pad */

extern "C" void kernel_launch(void* const* d_in, const int* in_sizes, int n_in,
                              void* d_out, int out_size) {
    const float* cd   = (const float*)d_in[0];
    const float* gi   = (const float*)d_in[1];
    const int*   nact = (const int*)d_in[2];

    float* out = (float*)d_out;                  // [2, B, P] float32

    dim3 tb(32, 8);
    dim3 gb(P_ / 32, G_ / 32, B_);
    cost_transpose_kernel<<<gb, tb>>>(cd, gi);

    cudaFuncSetAttribute(matcher_kernel,
                         cudaFuncAttributeMaxDynamicSharedMemorySize, MATCHER_SMEM);

    cudaLaunchConfig_t cfg = {};
    cfg.gridDim = dim3(B_);
    cfg.blockDim = dim3(NT);
    cfg.dynamicSmemBytes = MATCHER_SMEM;
    cfg.stream = 0;
    cudaLaunchAttribute attr[1];
    attr[0].id = cudaLaunchAttributeProgrammaticStreamSerialization;
    attr[0].val.programmaticStreamSerializationAllowed = 1;
    cfg.attrs = attr;
    cfg.numAttrs = 1;
    cudaLaunchKernelEx(&cfg, matcher_kernel, nact, out);
}